// round 15
// baseline (speedup 1.0000x reference)
#include <cuda_runtime.h>
#include <cuda_fp16.h>
#include <math.h>
#include <stdint.h>

#define S_LEN   2048
#define BATCH   2
#define HDIM    2048
#define NHEADS  16
#define MROWS   (BATCH * S_LEN)   // 4096

// ---------------- scratch ----------------
__device__ __half g_wh[8650752];   // transposed half weights
__device__ __half g_hs[8388608];   // hs [4096][2048]
__device__ __half g_p1[6291456];   // [4096][1536]; only cols 0..512 used now
__device__ __half g_q [8388608];   // [m][h*128+d]
__device__ __half g_k [8388608];
__device__ __half g_vt[8388608];   // TRANSPOSED: [n=2048][m=4096]
__device__ __half g_y [8388608];
__device__ float  g_cs[65536];     // rope cos table [s][jj]  (2048 x 32)
__device__ float  g_sn[65536];     // rope sin table

#define WCAT_OFF 0u         // [1536][2048]
#define WKU_OFF  3145728u   // [1024][256]
#define WQU_OFF  3407872u
#define WRQ_OFF  3670016u
#define WVU_OFF  3932160u   // [2048][256]
#define WO_OFF   4456448u   // [2048][2048]

// ---------------- helpers ----------------
__device__ __forceinline__ void mma_f16(float* c, const uint32_t* a, const uint32_t* b) {
    asm volatile(
        "mma.sync.aligned.m16n8k16.row.col.f32.f16.f16.f32 "
        "{%0,%1,%2,%3}, {%4,%5,%6,%7}, {%8,%9}, {%0,%1,%2,%3};\n"
        : "+f"(c[0]), "+f"(c[1]), "+f"(c[2]), "+f"(c[3])
        : "r"(a[0]), "r"(a[1]), "r"(a[2]), "r"(a[3]), "r"(b[0]), "r"(b[1]));
}
__device__ __forceinline__ void ldsm4(uint32_t* r, uint32_t addr) {
    asm volatile("ldmatrix.sync.aligned.m8n8.x4.shared.b16 {%0,%1,%2,%3}, [%4];"
        : "=r"(r[0]), "=r"(r[1]), "=r"(r[2]), "=r"(r[3]) : "r"(addr));
}
__device__ __forceinline__ uint32_t pack2(float a, float b) {
    __half2 h = __floats2half2_rn(a, b);
    return *(uint32_t*)&h;
}
__device__ __forceinline__ uint32_t smem_u32(const void* p) {
    uint32_t a;
    asm("{ .reg .u64 t; cvta.to.shared.u64 t, %1; cvt.u32.u64 %0, t; }" : "=r"(a) : "l"(p));
    return a;
}
__device__ __forceinline__ void cp16(uint32_t dst, const void* src) {
    asm volatile("cp.async.cg.shared.global [%0], [%1], 16;" :: "r"(dst), "l"(src));
}
__device__ __forceinline__ void cp_commit() {
    asm volatile("cp.async.commit_group;" ::: "memory");
}
template<int N>
__device__ __forceinline__ void cp_wait() {
    asm volatile("cp.async.wait_group %0;" :: "n"(N) : "memory");
}

// ---------------- fused setup: weight transpose + hs convert + rope table ----
__global__ void setup_kernel(
    const float* __restrict__ hs,
    const float* __restrict__ wkv, const float* __restrict__ wqd,
    const float* __restrict__ wrk, const float* __restrict__ wku,
    const float* __restrict__ wqu, const float* __restrict__ wrq,
    const float* __restrict__ wvu, const float* __restrict__ wo,
    __half* __restrict__ wh, __half* __restrict__ dhs)
{
    const int b  = blockIdx.x;
    const int tx = threadIdx.x;
    const int ty = threadIdx.y;
    const int lt = ty * 32 + tx;

    if (b >= 12544) {                      // rope table: 256 blocks
        int idx = (b - 12544) * 256 + lt;  // [0, 65536)
        int s = idx >> 5, jj = idx & 31;
        float inv = exp2f(-0.41524101186092f * (float)jj);
        float sn, cs;
        sincosf((float)s * inv, &sn, &cs);
        g_cs[idx] = cs; g_sn[idx] = sn;
        return;
    }
    if (b >= 8448) {                       // hs -> half
        int i = (b - 8448) * 256 + lt;
        float4 a = ((const float4*)hs)[2 * i];
        float4 c = ((const float4*)hs)[2 * i + 1];
        uint4 u;
        u.x = pack2(a.x, a.y); u.y = pack2(a.z, a.w);
        u.z = pack2(c.x, c.y); u.w = pack2(c.z, c.w);
        *(uint4*)&dhs[8 * i] = u;
        return;
    }

    __shared__ float tile[32][33];
    const float* src; int ld, k0, n0, dK; uint32_t doff;
    if (b < 3072) {
        k0 = (b / 48) * 32; n0 = (b % 48) * 32; doff = WCAT_OFF; dK = 2048;
        if (n0 < 256)      { src = wkv + n0;         ld = 256; }
        else if (n0 < 512) { src = wqd + (n0 - 256); ld = 256; }
        else               { src = wrk + (n0 - 512); ld = 1024; }
    } else if (b < 3328) { int l = b - 3072; k0 = (l / 32) * 32; n0 = (l % 32) * 32;
        src = wku + n0; ld = 1024; doff = WKU_OFF; dK = 256;
    } else if (b < 3584) { int l = b - 3328; k0 = (l / 32) * 32; n0 = (l % 32) * 32;
        src = wqu + n0; ld = 1024; doff = WQU_OFF; dK = 256;
    } else if (b < 3840) { int l = b - 3584; k0 = (l / 32) * 32; n0 = (l % 32) * 32;
        src = wrq + n0; ld = 1024; doff = WRQ_OFF; dK = 256;
    } else if (b < 4352) { int l = b - 3840; k0 = (l / 64) * 32; n0 = (l % 64) * 32;
        src = wvu + n0; ld = 2048; doff = WVU_OFF; dK = 256;
    } else {               int l = b - 4352; k0 = (l / 64) * 32; n0 = (l % 64) * 32;
        src = wo + n0;  ld = 2048; doff = WO_OFF;  dK = 2048;
    }
#pragma unroll
    for (int rr = 0; rr < 4; rr++) {
        int r = ty * 4 + rr;
        tile[r][tx] = src[(size_t)(k0 + r) * ld + tx];
    }
    __syncthreads();
#pragma unroll
    for (int rr = 0; rr < 4; rr++) {
        int r = ty * 4 + rr;
        wh[doff + (size_t)(n0 + r) * dK + k0 + tx] = __float2half_rn(tile[tx][r]);
    }
}

// ---------------- fp16 GEMM: 128x128 tile, 4 warps x (64x64), ldmatrix ------
#define HKP 40
#define HSTG (2 * 128 * HKP)
#define GEMM_SMEM (4 * HSTG * 2)    // 81920 B

// mode: 0 half plain, 1 half split, 2 f32 plain, 3 half V-transposed,
//       4 half rope-split
__device__ __forceinline__ void gemm_f16_body(
    const __half* __restrict__ A, int lda,
    const __half* __restrict__ B, int ldb,
    void* Cv, int ldc, int K, int mode, int roff,
    int bm, int bn, __half* smem)
{
    const uint32_t sb = smem_u32(smem);
    const int tid  = threadIdx.x;
    const int lane = tid & 31;
    const int wid  = tid >> 5;
    const int wm   = (wid & 1) * 64;
    const int wn   = (wid >> 1) * 64;
    const int g    = lane >> 2;
    const int j    = lane & 3;

    const int ra  = lane & 15;
    const int ka  = (lane >> 4) << 3;
    const int nb  = ((lane >> 4) << 3) + (lane & 7);
    const int kbo = lane & 8;

    float acc[4][8][4];
#pragma unroll
    for (int mt = 0; mt < 4; mt++)
#pragma unroll
        for (int nt = 0; nt < 8; nt++)
#pragma unroll
            for (int e = 0; e < 4; e++) acc[mt][nt][e] = 0.f;

    const int nstage = K >> 5;

    auto issue = [&](int it) {
        const int k0 = it << 5;
        const uint32_t base = sb + ((it & 3) * HSTG) * 2;
#pragma unroll
        for (int i = 0; i < 4; i++) {
            int f = tid + (i << 7);
            int r = f >> 2, c = f & 3;
            cp16(base + (uint32_t)(r * HKP + c * 8) * 2,
                 A + (size_t)(bm + r) * lda + k0 + c * 8);
        }
#pragma unroll
        for (int i = 0; i < 4; i++) {
            int f = tid + (i << 7);
            int r = f >> 2, c = f & 3;
            cp16(base + (uint32_t)(128 * HKP + r * HKP + c * 8) * 2,
                 B + (size_t)(bn + r) * ldb + k0 + c * 8);
        }
        cp_commit();
    };

    issue(0);
    if (nstage > 1) issue(1);
    if (nstage > 2) issue(2);

    for (int it = 0; it < nstage; it++) {
        if (it + 3 < nstage) issue(it + 3);
        else cp_commit();
        cp_wait<3>();
        __syncthreads();

        const uint32_t sA = sb + ((it & 3) * HSTG) * 2;
        const uint32_t sB = sA + 128 * HKP * 2;
#pragma unroll
        for (int s = 0; s < 2; s++) {
            const int kb = s * 16;
            uint32_t af[4][4], bf[4][4];
#pragma unroll
            for (int mt = 0; mt < 4; mt++)
                ldsm4(af[mt], sA + (uint32_t)((wm + mt * 16 + ra) * HKP + kb + ka) * 2);
#pragma unroll
            for (int p = 0; p < 4; p++)
                ldsm4(bf[p], sB + (uint32_t)((wn + p * 16 + nb) * HKP + kb + kbo) * 2);
#pragma unroll
            for (int mt = 0; mt < 4; mt++)
#pragma unroll
                for (int p = 0; p < 4; p++) {
                    mma_f16(acc[mt][2 * p],     af[mt], &bf[p][0]);
                    mma_f16(acc[mt][2 * p + 1], af[mt], &bf[p][2]);
                }
        }
        __syncthreads();
    }

    // ---------------- epilogue ----------------
    if (mode == 4) {
        __half* C = (__half*)Cv;
#pragma unroll
        for (int mt = 0; mt < 4; mt++) {
            const int row = bm + wm + mt * 16 + g;
            const int s0 = row & 2047, s1 = (row + 8) & 2047;
#pragma unroll
            for (int nt = 0; nt < 4; nt++) {
                const int nr = bn + wn + nt * 8 + 2 * j - roff;
                const int jj = nr & 63;
                const int colx = ((nr >> 6) << 7) + jj + 64;
                const float c00 = g_cs[s0 * 32 + jj],     n00 = g_sn[s0 * 32 + jj];
                const float c01 = g_cs[s0 * 32 + jj + 1], n01 = g_sn[s0 * 32 + jj + 1];
                const float c10 = g_cs[s1 * 32 + jj],     n10 = g_sn[s1 * 32 + jj];
                const float c11 = g_cs[s1 * 32 + jj + 1], n11 = g_sn[s1 * 32 + jj + 1];
                float x1a = acc[mt][nt][0],     x1b = acc[mt][nt][1];
                float x2a = acc[mt][nt + 4][0], x2b = acc[mt][nt + 4][1];
                *(uint32_t*)(C + (size_t)row * ldc + colx) =
                    pack2(x1a * c00 - x2a * n00, x1b * c01 - x2b * n01);
                *(uint32_t*)(C + (size_t)row * ldc + colx + 32) =
                    pack2(x2a * c00 + x1a * n00, x2b * c01 + x1b * n01);
                x1a = acc[mt][nt][2];     x1b = acc[mt][nt][3];
                x2a = acc[mt][nt + 4][2]; x2b = acc[mt][nt + 4][3];
                *(uint32_t*)(C + (size_t)(row + 8) * ldc + colx) =
                    pack2(x1a * c10 - x2a * n10, x1b * c11 - x2b * n11);
                *(uint32_t*)(C + (size_t)(row + 8) * ldc + colx + 32) =
                    pack2(x2a * c10 + x1a * n10, x2b * c11 + x1b * n11);
            }
        }
        return;
    }
#pragma unroll
    for (int mt = 0; mt < 4; mt++) {
        const int row = bm + wm + mt * 16 + g;
#pragma unroll
        for (int nt = 0; nt < 8; nt++) {
            const int n = bn + wn + nt * 8 + 2 * j;
            if (mode == 3) {
                __half* vt = (__half*)Cv;
                vt[(size_t)n * 4096 + row]           = __float2half_rn(acc[mt][nt][0]);
                vt[(size_t)(n + 1) * 4096 + row]     = __float2half_rn(acc[mt][nt][1]);
                vt[(size_t)n * 4096 + row + 8]       = __float2half_rn(acc[mt][nt][2]);
                vt[(size_t)(n + 1) * 4096 + row + 8] = __float2half_rn(acc[mt][nt][3]);
            } else if (mode == 2) {
                float* C = (float*)Cv;
                *(float2*)(C + (size_t)row * ldc + n) =
                    make_float2(acc[mt][nt][0], acc[mt][nt][1]);
                *(float2*)(C + (size_t)(row + 8) * ldc + n) =
                    make_float2(acc[mt][nt][2], acc[mt][nt][3]);
            } else {
                const int col = (mode == 1) ? (((n >> 6) << 7) + (n & 63)) : n;
                __half* C = (__half*)Cv;
                *(uint32_t*)(C + (size_t)row * ldc + col) = pack2(acc[mt][nt][0], acc[mt][nt][1]);
                *(uint32_t*)(C + (size_t)(row + 8) * ldc + col) = pack2(acc[mt][nt][2], acc[mt][nt][3]);
            }
        }
    }
}

__global__ void __launch_bounds__(128, 2) f16_gemm_kernel(
    const __half* A, int lda, const __half* B, int ldb,
    void* C, int ldc, int K, int mode)
{
    extern __shared__ __half smh[];
    gemm_f16_body(A, lda, B, ldb, C, ldc, K, mode, 0,
                  blockIdx.y * 128, blockIdx.x * 128, smh);
}

__global__ void __launch_bounds__(128, 2) downproj_kernel(
    const __half* __restrict__ hs, const __half* __restrict__ wh,
    __half* __restrict__ p1, __half* __restrict__ k)
{
    extern __shared__ __half smh[];
    const int bx = blockIdx.x;
    const int bm = blockIdx.y * 128;
    if (bx < 4)
        gemm_f16_body(hs, HDIM, wh + WCAT_OFF, 2048, p1, 1536, 2048, 0, 0,
                      bm, bx << 7, smh);
    else
        gemm_f16_body(hs, HDIM, wh + WCAT_OFF, 2048, k, HDIM, 2048, 4, 512,
                      bm, bx << 7, smh);
}

__global__ void __launch_bounds__(128, 2) upproj_kernel(
    const __half* __restrict__ p1, const __half* __restrict__ wh,
    __half* __restrict__ k, __half* __restrict__ q, __half* __restrict__ vt)
{
    extern __shared__ __half smh[];
    const int bx = blockIdx.x;
    const int bm = blockIdx.y * 128;
    const __half* A;
    const __half* B;
    void* C;
    int ldc, bn, mode;
    if (bx < 8) {
        A = p1;       B = wh + WKU_OFF; C = k;  ldc = HDIM; bn = bx << 7;        mode = 1;
    } else if (bx < 16) {
        A = p1 + 256; B = wh + WQU_OFF; C = q;  ldc = HDIM; bn = (bx - 8) << 7;  mode = 1;
    } else if (bx < 24) {
        A = p1 + 256; B = wh + WRQ_OFF; C = q;  ldc = HDIM; bn = (bx - 16) << 7; mode = 4;
    } else {
        A = p1;       B = wh + WVU_OFF; C = vt; ldc = 0;    bn = (bx - 24) << 7; mode = 3;
    }
    gemm_f16_body(A, 1536, B, 256, C, ldc, 256, mode, 0, bm, bn, smh);
}

// ---------------- Flash attention: BQ=64, software-pipelined, 2 CTAs/SM -----
// Triple-buffered K/V; QK(t+1) overlapped with softmax(t); one sync per tile.
// smem halves: K 3x[64][136]=26112, V 3x[128][72]=27648; total 53760 h.
#define FKB(t) (sb + (uint32_t)(((t) % 3) * 8704) * 2)
#define FVB(t) (sb + (uint32_t)(26112 + ((t) % 3) * 9216) * 2)
#define FLASH_SMEM (53760 * 2)

__global__ void __launch_bounds__(128, 2) flash_f16_kernel(
    const __half* __restrict__ Q, const __half* __restrict__ Kp,
    const __half* __restrict__ Vt, __half* __restrict__ Y)
{
    extern __shared__ __half smh[];
    const uint32_t sb = smem_u32(smh);

    const int tid  = threadIdx.x;
    const int lane = tid & 31;
    const int w    = tid >> 5;          // 0..3
    const int g    = lane >> 2;
    const int j    = lane & 3;
    const int bh   = blockIdx.y;
    const int b    = bh >> 4;
    const int h    = bh & 15;
    const int qt   = (int)gridDim.x - 1 - (int)blockIdx.x;
    const int q0   = qt << 6;
    const float scale = 0.08838834764831845f;

    const int ra  = lane & 15;
    const int ka  = (lane >> 4) << 3;
    const int nb  = ((lane >> 4) << 3) + (lane & 7);
    const int kbo = lane & 8;

    const __half* Kbase = Kp + (size_t)b * S_LEN * HDIM + h * 128;
    const __half* Vtb   = Vt + (size_t)h * 128 * 4096 + b * S_LEN;
    const int nkv = qt + 1;

    // ---- stage Q [64][136] transiently into K-buf0, extract A-frags
    const __half* Qg = Q + (size_t)(b * S_LEN + q0) * HDIM + h * 128;
#pragma unroll
    for (int i = 0; i < 8; i++) {
        int f = tid + (i << 7);
        int r = f >> 4, c = f & 15;
        cp16(sb + (uint32_t)(r * 136 + c * 8) * 2, Qg + (size_t)r * HDIM + c * 8);
    }
    cp_commit();
    cp_wait<0>();
    __syncthreads();

    uint32_t qa[8][4];
#pragma unroll
    for (int ks = 0; ks < 8; ks++)
        ldsm4(qa[ks], sb + (uint32_t)((w * 16 + ra) * 136 + ks * 16 + ka) * 2);
    __syncthreads();  // all warps done reading Q before kv(0) overwrites buf0

    auto issue_kv = [&](int t) {
        const int kv0 = t << 6;
        const uint32_t kb = FKB(t);
        const uint32_t vb = FVB(t);
#pragma unroll
        for (int i = 0; i < 8; i++) {
            int f = tid + (i << 7);
            int r = f >> 4, c = f & 15;
            cp16(kb + (uint32_t)(r * 136 + c * 8) * 2,
                 Kbase + (size_t)(kv0 + r) * HDIM + c * 8);
        }
#pragma unroll
        for (int i = 0; i < 8; i++) {
            int f = tid + (i << 7);
            int r = f >> 3, c = f & 7;
            cp16(vb + (uint32_t)(r * 72 + c * 8) * 2,
                 Vtb + (size_t)r * 4096 + kv0 + c * 8);
        }
        cp_commit();
    };

    float o[16][4];
#pragma unroll
    for (int nt = 0; nt < 16; nt++)
#pragma unroll
        for (int e = 0; e < 4; e++) o[nt][e] = 0.f;
    float m0 = -1e30f, m1 = -1e30f, l0 = 0.f, l1 = 0.f;
    const int gr0 = q0 + w * 16 + g;
    const int gr1 = gr0 + 8;

    float s0[8][4], s1[8][4];

    // QK into SD from K buffer of tile TI
#define FLASH_QK(TI, SD) do { \
        const uint32_t sbK = FKB(TI); \
        _Pragma("unroll") \
        for (int nt = 0; nt < 8; nt++) { \
            SD[nt][0] = 0.f; SD[nt][1] = 0.f; SD[nt][2] = 0.f; SD[nt][3] = 0.f; } \
        _Pragma("unroll") \
        for (int ks = 0; ks < 8; ks++) { \
            const int kc = ks * 16; \
            uint32_t bf[4][4]; \
            _Pragma("unroll") \
            for (int p = 0; p < 4; p++) \
                ldsm4(bf[p], sbK + (uint32_t)((p * 16 + nb) * 136 + kc + kbo) * 2); \
            _Pragma("unroll") \
            for (int p = 0; p < 4; p++) { \
                mma_f16(SD[2 * p],     qa[ks], &bf[p][0]); \
                mma_f16(SD[2 * p + 1], qa[ks], &bf[p][2]); \
            } \
        } \
    } while (0)

    // one pipeline step: prefetch+QK(t+1) into SN, then softmax(t)+PV(t) on SC
#define FLASH_STEP(T, SC, SN) do { \
        if ((T) + 1 < nkv) { \
            cp_wait<0>(); \
            __syncthreads(); \
            if ((T) + 2 < nkv) issue_kv((T) + 2); \
            FLASH_QK((T) + 1, SN); \
        } \
        const int kv0 = (T) << 6; \
        const bool needm = ((T) == nkv - 1); \
        float tm0 = -1e30f, tm1 = -1e30f; \
        _Pragma("unroll") \
        for (int nt = 0; nt < 8; nt++) { \
            int c0 = kv0 + nt * 8 + 2 * j; \
            _Pragma("unroll") \
            for (int e = 0; e < 2; e++) { \
                float v0 = SC[nt][e] * scale; \
                float v1 = SC[nt][2 + e] * scale; \
                if (needm) { \
                    if (c0 + e > gr0) v0 = -1e30f; \
                    if (c0 + e > gr1) v1 = -1e30f; \
                } \
                SC[nt][e] = v0; SC[nt][2 + e] = v1; \
                tm0 = fmaxf(tm0, v0); tm1 = fmaxf(tm1, v1); \
            } \
        } \
        tm0 = fmaxf(tm0, __shfl_xor_sync(0xffffffffu, tm0, 1)); \
        tm0 = fmaxf(tm0, __shfl_xor_sync(0xffffffffu, tm0, 2)); \
        tm1 = fmaxf(tm1, __shfl_xor_sync(0xffffffffu, tm1, 1)); \
        tm1 = fmaxf(tm1, __shfl_xor_sync(0xffffffffu, tm1, 2)); \
        const bool up0 = tm0 > m0, up1 = tm1 > m1; \
        const float mn0 = up0 ? tm0 : m0; \
        const float mn1 = up1 ? tm1 : m1; \
        const float cr0 = up0 ? __expf(m0 - mn0) : 1.f; \
        const float cr1 = up1 ? __expf(m1 - mn1) : 1.f; \
        float sum0 = 0.f, sum1 = 0.f; \
        _Pragma("unroll") \
        for (int nt = 0; nt < 8; nt++) { \
            float p0 = __expf(SC[nt][0] - mn0); \
            float p1 = __expf(SC[nt][1] - mn0); \
            float p2 = __expf(SC[nt][2] - mn1); \
            float p3 = __expf(SC[nt][3] - mn1); \
            sum0 += p0 + p1; sum1 += p2 + p3; \
            SC[nt][0] = p0; SC[nt][1] = p1; SC[nt][2] = p2; SC[nt][3] = p3; \
        } \
        sum0 += __shfl_xor_sync(0xffffffffu, sum0, 1); \
        sum0 += __shfl_xor_sync(0xffffffffu, sum0, 2); \
        sum1 += __shfl_xor_sync(0xffffffffu, sum1, 1); \
        sum1 += __shfl_xor_sync(0xffffffffu, sum1, 2); \
        l0 = l0 * cr0 + sum0; l1 = l1 * cr1 + sum1; \
        m0 = mn0; m1 = mn1; \
        if (__any_sync(0xffffffffu, up0 || up1)) { \
            _Pragma("unroll") \
            for (int nt = 0; nt < 16; nt++) { \
                o[nt][0] *= cr0; o[nt][1] *= cr0; \
                o[nt][2] *= cr1; o[nt][3] *= cr1; \
            } \
        } \
        const uint32_t sbV = FVB(T); \
        _Pragma("unroll") \
        for (int kk = 0; kk < 4; kk++) { \
            uint32_t pa[4]; \
            pa[0] = pack2(SC[2 * kk][0],     SC[2 * kk][1]); \
            pa[1] = pack2(SC[2 * kk][2],     SC[2 * kk][3]); \
            pa[2] = pack2(SC[2 * kk + 1][0], SC[2 * kk + 1][1]); \
            pa[3] = pack2(SC[2 * kk + 1][2], SC[2 * kk + 1][3]); \
            const int kc = kk * 16; \
            uint32_t bv[4]; \
            _Pragma("unroll") \
            for (int p = 0; p < 8; p++) { \
                ldsm4(bv, sbV + (uint32_t)((p * 16 + nb) * 72 + kc + kbo) * 2); \
                mma_f16(o[2 * p],     pa, &bv[0]); \
                mma_f16(o[2 * p + 1], pa, &bv[2]); \
            } \
        } \
    } while (0)

    // prologue: issue kv(0), kv(1); QK(0)
    issue_kv(0);
    if (nkv > 1) issue_kv(1);
    cp_wait<0>();
    __syncthreads();
    FLASH_QK(0, s0);

    int t = 0;
    while (true) {
        FLASH_STEP(t, s0, s1);
        if (++t >= nkv) break;
        FLASH_STEP(t, s1, s0);
        if (++t >= nkv) break;
    }

#undef FLASH_STEP
#undef FLASH_QK

    // ---- epilogue -> y half
    const float inv0 = 1.f / l0, inv1 = 1.f / l1;
    __half* Y0 = Y + (size_t)(b * S_LEN + gr0) * HDIM + h * 128;
    __half* Y1 = Y + (size_t)(b * S_LEN + gr0 + 8) * HDIM + h * 128;
#pragma unroll
    for (int nt = 0; nt < 16; nt++) {
        const int c = nt * 8 + 2 * j;
        *(uint32_t*)&Y0[c] = pack2(o[nt][0] * inv0, o[nt][1] * inv0);
        *(uint32_t*)&Y1[c] = pack2(o[nt][2] * inv1, o[nt][3] * inv1);
    }
}

// ---------------- launch ----------------
extern "C" void kernel_launch(void* const* d_in, const int* in_sizes, int n_in,
                              void* d_out, int out_size)
{
    const float* hs   = (const float*)d_in[0];
    const float* Wkv  = (const float*)d_in[1];
    const float* Wq_d = (const float*)d_in[2];
    const float* Wk_u = (const float*)d_in[3];
    const float* Wq_u = (const float*)d_in[4];
    const float* Wv_u = (const float*)d_in[5];
    const float* Wrk  = (const float*)d_in[6];
    const float* Wrq  = (const float*)d_in[7];
    const float* Wo   = (const float*)d_in[8];
    float* out = (float*)d_out;

    __half *p_wh, *p_hs, *p_p1, *p_q, *p_k, *p_vt, *p_y;
    cudaGetSymbolAddress((void**)&p_wh, g_wh);
    cudaGetSymbolAddress((void**)&p_hs, g_hs);
    cudaGetSymbolAddress((void**)&p_p1, g_p1);
    cudaGetSymbolAddress((void**)&p_q, g_q);
    cudaGetSymbolAddress((void**)&p_k, g_k);
    cudaGetSymbolAddress((void**)&p_vt, g_vt);
    cudaGetSymbolAddress((void**)&p_y, g_y);

    cudaFuncSetAttribute(f16_gemm_kernel,
                         cudaFuncAttributeMaxDynamicSharedMemorySize, GEMM_SMEM);
    cudaFuncSetAttribute(downproj_kernel,
                         cudaFuncAttributeMaxDynamicSharedMemorySize, GEMM_SMEM);
    cudaFuncSetAttribute(upproj_kernel,
                         cudaFuncAttributeMaxDynamicSharedMemorySize, GEMM_SMEM);
    cudaFuncSetAttribute(flash_f16_kernel,
                         cudaFuncAttributeMaxDynamicSharedMemorySize, FLASH_SMEM);

    // 1. fused setup
    setup_kernel<<<12800, dim3(32, 8)>>>(hs, Wkv, Wq_d, Wrk, Wk_u, Wq_u,
                                         Wrq, Wv_u, Wo, p_wh, p_hs);

    // 2. down-projection (kv_d|q_d -> p1, k_r rope -> g_k)
    downproj_kernel<<<dim3(12, 32), 128, GEMM_SMEM>>>(p_hs, p_wh, p_p1, p_k);

    // 3. up-projections (k_c, q_c, q_r rope, v transposed)
    upproj_kernel<<<dim3(40, 32), 128, GEMM_SMEM>>>(p_p1, p_wh, p_k, p_q, p_vt);

    // 4. causal flash attention (BQ=64, pipelined, 2 CTAs/SM)
    flash_f16_kernel<<<dim3(S_LEN / 64, BATCH * NHEADS), 128, FLASH_SMEM>>>(
        p_q, p_k, p_vt, p_y);

    // 5. output projection -> f32 out
    f16_gemm_kernel<<<dim3(16, 32), 128, GEMM_SMEM>>>(
        p_y, HDIM, p_wh + WO_OFF, 2048, out, HDIM, 2048, 2);
}

// round 16
// speedup vs baseline: 1.0004x; 1.0004x over previous
#include <cuda_runtime.h>
#include <cuda_fp16.h>
#include <math.h>
#include <stdint.h>

#define S_LEN   2048
#define BATCH   2
#define HDIM    2048
#define NHEADS  16
#define MROWS   (BATCH * S_LEN)   // 4096
#define ATT_SCALE 0.08838834764831845f

// ---------------- scratch ----------------
__device__ __half g_wh[8650752];   // transposed half weights
__device__ __half g_hs[8388608];   // hs [4096][2048]
__device__ __half g_p1[6291456];   // [4096][1536]; only cols 0..512 used now
__device__ __half g_q [8388608];   // [m][h*128+d]  (PRE-SCALED by 1/sqrt(d))
__device__ __half g_k [8388608];
__device__ __half g_vt[8388608];   // TRANSPOSED: [n=2048][m=4096]
__device__ __half g_y [8388608];
__device__ float  g_cs[65536];     // rope cos table [s][jj]  (2048 x 32)
__device__ float  g_sn[65536];     // rope sin table

#define WCAT_OFF 0u         // [1536][2048]
#define WKU_OFF  3145728u   // [1024][256]
#define WQU_OFF  3407872u
#define WRQ_OFF  3670016u
#define WVU_OFF  3932160u   // [2048][256]
#define WO_OFF   4456448u   // [2048][2048]

// ---------------- helpers ----------------
__device__ __forceinline__ void mma_f16(float* c, const uint32_t* a, const uint32_t* b) {
    asm volatile(
        "mma.sync.aligned.m16n8k16.row.col.f32.f16.f16.f32 "
        "{%0,%1,%2,%3}, {%4,%5,%6,%7}, {%8,%9}, {%0,%1,%2,%3};\n"
        : "+f"(c[0]), "+f"(c[1]), "+f"(c[2]), "+f"(c[3])
        : "r"(a[0]), "r"(a[1]), "r"(a[2]), "r"(a[3]), "r"(b[0]), "r"(b[1]));
}
__device__ __forceinline__ void ldsm4(uint32_t* r, uint32_t addr) {
    asm volatile("ldmatrix.sync.aligned.m8n8.x4.shared.b16 {%0,%1,%2,%3}, [%4];"
        : "=r"(r[0]), "=r"(r[1]), "=r"(r[2]), "=r"(r[3]) : "r"(addr));
}
__device__ __forceinline__ uint32_t pack2(float a, float b) {
    __half2 h = __floats2half2_rn(a, b);
    return *(uint32_t*)&h;
}
__device__ __forceinline__ uint32_t smem_u32(const void* p) {
    uint32_t a;
    asm("{ .reg .u64 t; cvta.to.shared.u64 t, %1; cvt.u32.u64 %0, t; }" : "=r"(a) : "l"(p));
    return a;
}
__device__ __forceinline__ void cp16(uint32_t dst, const void* src) {
    asm volatile("cp.async.cg.shared.global [%0], [%1], 16;" :: "r"(dst), "l"(src));
}
__device__ __forceinline__ void cp_commit() {
    asm volatile("cp.async.commit_group;" ::: "memory");
}
template<int N>
__device__ __forceinline__ void cp_wait() {
    asm volatile("cp.async.wait_group %0;" :: "n"(N) : "memory");
}

// ---------------- fused setup: weight transpose + hs convert + rope table ----
__global__ void setup_kernel(
    const float* __restrict__ hs,
    const float* __restrict__ wkv, const float* __restrict__ wqd,
    const float* __restrict__ wrk, const float* __restrict__ wku,
    const float* __restrict__ wqu, const float* __restrict__ wrq,
    const float* __restrict__ wvu, const float* __restrict__ wo,
    __half* __restrict__ wh, __half* __restrict__ dhs)
{
    const int b  = blockIdx.x;
    const int tx = threadIdx.x;
    const int ty = threadIdx.y;
    const int lt = ty * 32 + tx;

    if (b >= 12544) {                      // rope table: 256 blocks
        int idx = (b - 12544) * 256 + lt;  // [0, 65536)
        int s = idx >> 5, jj = idx & 31;
        float inv = exp2f(-0.41524101186092f * (float)jj);
        float sn, cs;
        sincosf((float)s * inv, &sn, &cs);
        g_cs[idx] = cs; g_sn[idx] = sn;
        return;
    }
    if (b >= 8448) {                       // hs -> half
        int i = (b - 8448) * 256 + lt;
        float4 a = ((const float4*)hs)[2 * i];
        float4 c = ((const float4*)hs)[2 * i + 1];
        uint4 u;
        u.x = pack2(a.x, a.y); u.y = pack2(a.z, a.w);
        u.z = pack2(c.x, c.y); u.w = pack2(c.z, c.w);
        *(uint4*)&dhs[8 * i] = u;
        return;
    }

    __shared__ float tile[32][33];
    const float* src; int ld, k0, n0, dK; uint32_t doff;
    if (b < 3072) {
        k0 = (b / 48) * 32; n0 = (b % 48) * 32; doff = WCAT_OFF; dK = 2048;
        if (n0 < 256)      { src = wkv + n0;         ld = 256; }
        else if (n0 < 512) { src = wqd + (n0 - 256); ld = 256; }
        else               { src = wrk + (n0 - 512); ld = 1024; }
    } else if (b < 3328) { int l = b - 3072; k0 = (l / 32) * 32; n0 = (l % 32) * 32;
        src = wku + n0; ld = 1024; doff = WKU_OFF; dK = 256;
    } else if (b < 3584) { int l = b - 3328; k0 = (l / 32) * 32; n0 = (l % 32) * 32;
        src = wqu + n0; ld = 1024; doff = WQU_OFF; dK = 256;
    } else if (b < 3840) { int l = b - 3584; k0 = (l / 32) * 32; n0 = (l % 32) * 32;
        src = wrq + n0; ld = 1024; doff = WRQ_OFF; dK = 256;
    } else if (b < 4352) { int l = b - 3840; k0 = (l / 64) * 32; n0 = (l % 64) * 32;
        src = wvu + n0; ld = 2048; doff = WVU_OFF; dK = 256;
    } else {               int l = b - 4352; k0 = (l / 64) * 32; n0 = (l % 64) * 32;
        src = wo + n0;  ld = 2048; doff = WO_OFF;  dK = 2048;
    }
#pragma unroll
    for (int rr = 0; rr < 4; rr++) {
        int r = ty * 4 + rr;
        tile[r][tx] = src[(size_t)(k0 + r) * ld + tx];
    }
    __syncthreads();
#pragma unroll
    for (int rr = 0; rr < 4; rr++) {
        int r = ty * 4 + rr;
        wh[doff + (size_t)(n0 + r) * dK + k0 + tx] = __float2half_rn(tile[tx][r]);
    }
}

// ---------------- fp16 GEMM: 128x128 tile, 4 warps x (64x64), ldmatrix ------
#define HKP 40
#define HSTG (2 * 128 * HKP)
#define GEMM_SMEM (4 * HSTG * 2)    // 81920 B

// mode: 0 half plain, 1 half split, 2 f32 plain, 3 half V-transposed,
//       4 half rope-split.  oscale applied in modes 1 and 4.
__device__ __forceinline__ void gemm_f16_body(
    const __half* __restrict__ A, int lda,
    const __half* __restrict__ B, int ldb,
    void* Cv, int ldc, int K, int mode, int roff, float oscale,
    int bm, int bn, __half* smem)
{
    const uint32_t sb = smem_u32(smem);
    const int tid  = threadIdx.x;
    const int lane = tid & 31;
    const int wid  = tid >> 5;
    const int wm   = (wid & 1) * 64;
    const int wn   = (wid >> 1) * 64;
    const int g    = lane >> 2;
    const int j    = lane & 3;

    const int ra  = lane & 15;
    const int ka  = (lane >> 4) << 3;
    const int nb  = ((lane >> 4) << 3) + (lane & 7);
    const int kbo = lane & 8;

    float acc[4][8][4];
#pragma unroll
    for (int mt = 0; mt < 4; mt++)
#pragma unroll
        for (int nt = 0; nt < 8; nt++)
#pragma unroll
            for (int e = 0; e < 4; e++) acc[mt][nt][e] = 0.f;

    const int nstage = K >> 5;

    auto issue = [&](int it) {
        const int k0 = it << 5;
        const uint32_t base = sb + ((it & 3) * HSTG) * 2;
#pragma unroll
        for (int i = 0; i < 4; i++) {
            int f = tid + (i << 7);
            int r = f >> 2, c = f & 3;
            cp16(base + (uint32_t)(r * HKP + c * 8) * 2,
                 A + (size_t)(bm + r) * lda + k0 + c * 8);
        }
#pragma unroll
        for (int i = 0; i < 4; i++) {
            int f = tid + (i << 7);
            int r = f >> 2, c = f & 3;
            cp16(base + (uint32_t)(128 * HKP + r * HKP + c * 8) * 2,
                 B + (size_t)(bn + r) * ldb + k0 + c * 8);
        }
        cp_commit();
    };

    issue(0);
    if (nstage > 1) issue(1);
    if (nstage > 2) issue(2);

    for (int it = 0; it < nstage; it++) {
        if (it + 3 < nstage) issue(it + 3);
        else cp_commit();
        cp_wait<3>();
        __syncthreads();

        const uint32_t sA = sb + ((it & 3) * HSTG) * 2;
        const uint32_t sB = sA + 128 * HKP * 2;
#pragma unroll
        for (int s = 0; s < 2; s++) {
            const int kb = s * 16;
            uint32_t af[4][4], bf[4][4];
#pragma unroll
            for (int mt = 0; mt < 4; mt++)
                ldsm4(af[mt], sA + (uint32_t)((wm + mt * 16 + ra) * HKP + kb + ka) * 2);
#pragma unroll
            for (int p = 0; p < 4; p++)
                ldsm4(bf[p], sB + (uint32_t)((wn + p * 16 + nb) * HKP + kb + kbo) * 2);
#pragma unroll
            for (int mt = 0; mt < 4; mt++)
#pragma unroll
                for (int p = 0; p < 4; p++) {
                    mma_f16(acc[mt][2 * p],     af[mt], &bf[p][0]);
                    mma_f16(acc[mt][2 * p + 1], af[mt], &bf[p][2]);
                }
        }
        __syncthreads();
    }

    // ---------------- epilogue ----------------
    if (mode == 4) {
        __half* C = (__half*)Cv;
#pragma unroll
        for (int mt = 0; mt < 4; mt++) {
            const int row = bm + wm + mt * 16 + g;
            const int s0 = row & 2047, s1 = (row + 8) & 2047;
#pragma unroll
            for (int nt = 0; nt < 4; nt++) {
                const int nr = bn + wn + nt * 8 + 2 * j - roff;
                const int jj = nr & 63;
                const int colx = ((nr >> 6) << 7) + jj + 64;
                const float c00 = g_cs[s0 * 32 + jj],     n00 = g_sn[s0 * 32 + jj];
                const float c01 = g_cs[s0 * 32 + jj + 1], n01 = g_sn[s0 * 32 + jj + 1];
                const float c10 = g_cs[s1 * 32 + jj],     n10 = g_sn[s1 * 32 + jj];
                const float c11 = g_cs[s1 * 32 + jj + 1], n11 = g_sn[s1 * 32 + jj + 1];
                float x1a = acc[mt][nt][0] * oscale,     x1b = acc[mt][nt][1] * oscale;
                float x2a = acc[mt][nt + 4][0] * oscale, x2b = acc[mt][nt + 4][1] * oscale;
                *(uint32_t*)(C + (size_t)row * ldc + colx) =
                    pack2(x1a * c00 - x2a * n00, x1b * c01 - x2b * n01);
                *(uint32_t*)(C + (size_t)row * ldc + colx + 32) =
                    pack2(x2a * c00 + x1a * n00, x2b * c01 + x1b * n01);
                x1a = acc[mt][nt][2] * oscale;     x1b = acc[mt][nt][3] * oscale;
                x2a = acc[mt][nt + 4][2] * oscale; x2b = acc[mt][nt + 4][3] * oscale;
                *(uint32_t*)(C + (size_t)(row + 8) * ldc + colx) =
                    pack2(x1a * c10 - x2a * n10, x1b * c11 - x2b * n11);
                *(uint32_t*)(C + (size_t)(row + 8) * ldc + colx + 32) =
                    pack2(x2a * c10 + x1a * n10, x2b * c11 + x1b * n11);
            }
        }
        return;
    }
#pragma unroll
    for (int mt = 0; mt < 4; mt++) {
        const int row = bm + wm + mt * 16 + g;
#pragma unroll
        for (int nt = 0; nt < 8; nt++) {
            const int n = bn + wn + nt * 8 + 2 * j;
            if (mode == 3) {
                __half* vt = (__half*)Cv;
                vt[(size_t)n * 4096 + row]           = __float2half_rn(acc[mt][nt][0]);
                vt[(size_t)(n + 1) * 4096 + row]     = __float2half_rn(acc[mt][nt][1]);
                vt[(size_t)n * 4096 + row + 8]       = __float2half_rn(acc[mt][nt][2]);
                vt[(size_t)(n + 1) * 4096 + row + 8] = __float2half_rn(acc[mt][nt][3]);
            } else if (mode == 2) {
                float* C = (float*)Cv;
                *(float2*)(C + (size_t)row * ldc + n) =
                    make_float2(acc[mt][nt][0], acc[mt][nt][1]);
                *(float2*)(C + (size_t)(row + 8) * ldc + n) =
                    make_float2(acc[mt][nt][2], acc[mt][nt][3]);
            } else if (mode == 1) {
                const int col = ((n >> 6) << 7) + (n & 63);
                __half* C = (__half*)Cv;
                *(uint32_t*)(C + (size_t)row * ldc + col) =
                    pack2(acc[mt][nt][0] * oscale, acc[mt][nt][1] * oscale);
                *(uint32_t*)(C + (size_t)(row + 8) * ldc + col) =
                    pack2(acc[mt][nt][2] * oscale, acc[mt][nt][3] * oscale);
            } else {
                __half* C = (__half*)Cv;
                *(uint32_t*)(C + (size_t)row * ldc + n) = pack2(acc[mt][nt][0], acc[mt][nt][1]);
                *(uint32_t*)(C + (size_t)(row + 8) * ldc + n) = pack2(acc[mt][nt][2], acc[mt][nt][3]);
            }
        }
    }
}

__global__ void __launch_bounds__(128, 2) f16_gemm_kernel(
    const __half* A, int lda, const __half* B, int ldb,
    void* C, int ldc, int K, int mode)
{
    extern __shared__ __half smh[];
    gemm_f16_body(A, lda, B, ldb, C, ldc, K, mode, 0, 1.f,
                  blockIdx.y * 128, blockIdx.x * 128, smh);
}

__global__ void __launch_bounds__(128, 2) downproj_kernel(
    const __half* __restrict__ hs, const __half* __restrict__ wh,
    __half* __restrict__ p1, __half* __restrict__ k)
{
    extern __shared__ __half smh[];
    const int bx = blockIdx.x;
    const int bm = blockIdx.y * 128;
    if (bx < 4)
        gemm_f16_body(hs, HDIM, wh + WCAT_OFF, 2048, p1, 1536, 2048, 0, 0, 1.f,
                      bm, bx << 7, smh);
    else
        gemm_f16_body(hs, HDIM, wh + WCAT_OFF, 2048, k, HDIM, 2048, 4, 512, 1.f,
                      bm, bx << 7, smh);
}

__global__ void __launch_bounds__(128, 2) upproj_kernel(
    const __half* __restrict__ p1, const __half* __restrict__ wh,
    __half* __restrict__ k, __half* __restrict__ q, __half* __restrict__ vt)
{
    extern __shared__ __half smh[];
    const int bx = blockIdx.x;
    const int bm = blockIdx.y * 128;
    const __half* A;
    const __half* B;
    void* C;
    int ldc, bn, mode;
    float sc;
    if (bx < 8) {
        A = p1;       B = wh + WKU_OFF; C = k;  ldc = HDIM; bn = bx << 7;        mode = 1; sc = 1.f;
    } else if (bx < 16) {
        A = p1 + 256; B = wh + WQU_OFF; C = q;  ldc = HDIM; bn = (bx - 8) << 7;  mode = 1; sc = ATT_SCALE;
    } else if (bx < 24) {
        A = p1 + 256; B = wh + WRQ_OFF; C = q;  ldc = HDIM; bn = (bx - 16) << 7; mode = 4; sc = ATT_SCALE;
    } else {
        A = p1;       B = wh + WVU_OFF; C = vt; ldc = 0;    bn = (bx - 24) << 7; mode = 3; sc = 1.f;
    }
    gemm_f16_body(A, 1536, B, 256, C, ldc, 256, mode, 0, sc, bm, bn, smh);
}

// ---------------- Flash attention: BQ=64, 128 thr, 2 CTAs/SM ----------------
// Q pre-scaled by 1/sqrt(d). P in registers (A-frag layout) — no Ps smem.
// smem halves: Ks 2x[64][136], Vt 2x[128][72] = 35840 h = 71680 B
#define FKS0 0
#define FKS1 8704
#define FVT0 17408
#define FVT1 26624
#define FLASH_SMEM (35840 * 2)

__global__ void __launch_bounds__(128, 2) flash_f16_kernel(
    const __half* __restrict__ Q, const __half* __restrict__ Kp,
    const __half* __restrict__ Vt, __half* __restrict__ Y)
{
    extern __shared__ __half smh[];
    const uint32_t sb = smem_u32(smh);

    const int tid  = threadIdx.x;
    const int lane = tid & 31;
    const int w    = tid >> 5;          // 0..3
    const int g    = lane >> 2;
    const int j    = lane & 3;
    const int bh   = blockIdx.y;
    const int b    = bh >> 4;
    const int h    = bh & 15;
    const int qt   = (int)gridDim.x - 1 - (int)blockIdx.x;
    const int q0   = qt << 6;

    const int ra  = lane & 15;
    const int ka  = (lane >> 4) << 3;
    const int nb  = ((lane >> 4) << 3) + (lane & 7);
    const int kbo = lane & 8;

    const __half* Kbase = Kp + (size_t)b * S_LEN * HDIM + h * 128;
    const __half* Vtb   = Vt + (size_t)h * 128 * 4096 + b * S_LEN;

    // ---- stage Q [64][136] into Ks0 region, extract persistent A-frags
    const __half* Qg = Q + (size_t)(b * S_LEN + q0) * HDIM + h * 128;
#pragma unroll
    for (int i = 0; i < 8; i++) {
        int f = tid + (i << 7);
        int r = f >> 4, c = f & 15;
        cp16(sb + (uint32_t)(r * 136 + c * 8) * 2, Qg + (size_t)r * HDIM + c * 8);
    }
    cp_commit();
    cp_wait<0>();
    __syncthreads();

    uint32_t qa[8][4];
#pragma unroll
    for (int ks = 0; ks < 8; ks++)
        ldsm4(qa[ks], sb + (uint32_t)((w * 16 + ra) * 136 + ks * 16 + ka) * 2);
    __syncthreads();

    auto issue_kv = [&](int t) {
        const int d = t & 1;
        const int kv0 = t << 6;
        const uint32_t kb = sb + (d ? FKS1 : FKS0) * 2;
        const uint32_t vb = sb + (d ? FVT1 : FVT0) * 2;
#pragma unroll
        for (int i = 0; i < 8; i++) {
            int f = tid + (i << 7);
            int r = f >> 4, c = f & 15;
            cp16(kb + (uint32_t)(r * 136 + c * 8) * 2,
                 Kbase + (size_t)(kv0 + r) * HDIM + c * 8);
        }
#pragma unroll
        for (int i = 0; i < 8; i++) {
            int f = tid + (i << 7);
            int r = f >> 3, c = f & 7;
            cp16(vb + (uint32_t)(r * 72 + c * 8) * 2,
                 Vtb + (size_t)r * 4096 + kv0 + c * 8);
        }
        cp_commit();
    };

    float o[16][4];
#pragma unroll
    for (int nt = 0; nt < 16; nt++)
#pragma unroll
        for (int e = 0; e < 4; e++) o[nt][e] = 0.f;
    float m0 = -1e30f, m1 = -1e30f, l0 = 0.f, l1 = 0.f;

    const int nkv = qt + 1;
    issue_kv(0);

    for (int t = 0; t < nkv; t++) {
        const int kv0 = t << 6;
        if (t + 1 < nkv) issue_kv(t + 1);
        else cp_commit();
        cp_wait<1>();
        __syncthreads();

        const uint32_t sbK = sb + ((t & 1) ? FKS1 : FKS0) * 2;
        const uint32_t sbV = sb + ((t & 1) ? FVT1 : FVT0) * 2;

        // ---- S = Q K^T  (Q pre-scaled)
        float s[8][4];
#pragma unroll
        for (int nt = 0; nt < 8; nt++)
#pragma unroll
            for (int e = 0; e < 4; e++) s[nt][e] = 0.f;
#pragma unroll
        for (int ks = 0; ks < 8; ks++) {
            const int kc = ks * 16;
            uint32_t bf[4][4];
#pragma unroll
            for (int p = 0; p < 4; p++)
                ldsm4(bf[p], sbK + (uint32_t)((p * 16 + nb) * 136 + kc + kbo) * 2);
#pragma unroll
            for (int p = 0; p < 4; p++) {
                mma_f16(s[2 * p],     qa[ks], &bf[p][0]);
                mma_f16(s[2 * p + 1], qa[ks], &bf[p][2]);
            }
        }

        // ---- online softmax (fp32); P packed straight into A-frag registers
        const bool needm = (t == nkv - 1);
        const int gr0 = q0 + w * 16 + g;
        const int gr1 = gr0 + 8;
        float tm0 = -1e30f, tm1 = -1e30f;
#pragma unroll
        for (int nt = 0; nt < 8; nt++) {
            int c0 = kv0 + nt * 8 + 2 * j;
#pragma unroll
            for (int e = 0; e < 2; e++) {
                float v0 = s[nt][e];
                float v1 = s[nt][2 + e];
                if (needm) {
                    if (c0 + e > gr0) v0 = -1e30f;
                    if (c0 + e > gr1) v1 = -1e30f;
                }
                s[nt][e] = v0; s[nt][2 + e] = v1;
                tm0 = fmaxf(tm0, v0); tm1 = fmaxf(tm1, v1);
            }
        }
        tm0 = fmaxf(tm0, __shfl_xor_sync(0xffffffffu, tm0, 1));
        tm0 = fmaxf(tm0, __shfl_xor_sync(0xffffffffu, tm0, 2));
        tm1 = fmaxf(tm1, __shfl_xor_sync(0xffffffffu, tm1, 1));
        tm1 = fmaxf(tm1, __shfl_xor_sync(0xffffffffu, tm1, 2));
        const bool up0 = tm0 > m0, up1 = tm1 > m1;
        const float mn0 = up0 ? tm0 : m0;
        const float mn1 = up1 ? tm1 : m1;
        const float cr0 = up0 ? __expf(m0 - mn0) : 1.f;
        const float cr1 = up1 ? __expf(m1 - mn1) : 1.f;
        float sum0 = 0.f, sum1 = 0.f;
        uint32_t pa[4][4];   // A-fragments for PV: pa[kk] covers keys kk*16..+15
#pragma unroll
        for (int nt = 0; nt < 8; nt++) {
            float p0 = __expf(s[nt][0] - mn0);
            float p1 = __expf(s[nt][1] - mn0);
            float p2 = __expf(s[nt][2] - mn1);
            float p3 = __expf(s[nt][3] - mn1);
            sum0 += p0 + p1; sum1 += p2 + p3;
            const int kk = nt >> 1;
            if (nt & 1) { pa[kk][2] = pack2(p0, p1); pa[kk][3] = pack2(p2, p3); }
            else        { pa[kk][0] = pack2(p0, p1); pa[kk][1] = pack2(p2, p3); }
        }
        sum0 += __shfl_xor_sync(0xffffffffu, sum0, 1);
        sum0 += __shfl_xor_sync(0xffffffffu, sum0, 2);
        sum1 += __shfl_xor_sync(0xffffffffu, sum1, 1);
        sum1 += __shfl_xor_sync(0xffffffffu, sum1, 2);
        l0 = l0 * cr0 + sum0; l1 = l1 * cr1 + sum1;
        m0 = mn0; m1 = mn1;
        if (__any_sync(0xffffffffu, up0 || up1)) {
#pragma unroll
            for (int nt = 0; nt < 16; nt++) {
                o[nt][0] *= cr0; o[nt][1] *= cr0;
                o[nt][2] *= cr1; o[nt][3] *= cr1;
            }
        }

        // ---- O += P V  (P from registers; V via ldmatrix)
#pragma unroll
        for (int kk = 0; kk < 4; kk++) {
            const int kc = kk * 16;
            uint32_t bv[4];
#pragma unroll
            for (int p = 0; p < 8; p++) {
                ldsm4(bv, sbV + (uint32_t)((p * 16 + nb) * 72 + kc + kbo) * 2);
                mma_f16(o[2 * p],     pa[kk], &bv[0]);
                mma_f16(o[2 * p + 1], pa[kk], &bv[2]);
            }
        }
        __syncthreads();  // protect K/V buffers before next issue
    }

    // ---- epilogue -> y half
    const float inv0 = 1.f / l0, inv1 = 1.f / l1;
    const int gr0 = q0 + w * 16 + g;
    __half* Y0 = Y + (size_t)(b * S_LEN + gr0) * HDIM + h * 128;
    __half* Y1 = Y + (size_t)(b * S_LEN + gr0 + 8) * HDIM + h * 128;
#pragma unroll
    for (int nt = 0; nt < 16; nt++) {
        const int c = nt * 8 + 2 * j;
        *(uint32_t*)&Y0[c] = pack2(o[nt][0] * inv0, o[nt][1] * inv0);
        *(uint32_t*)&Y1[c] = pack2(o[nt][2] * inv1, o[nt][3] * inv1);
    }
}

// ---------------- launch ----------------
extern "C" void kernel_launch(void* const* d_in, const int* in_sizes, int n_in,
                              void* d_out, int out_size)
{
    const float* hs   = (const float*)d_in[0];
    const float* Wkv  = (const float*)d_in[1];
    const float* Wq_d = (const float*)d_in[2];
    const float* Wk_u = (const float*)d_in[3];
    const float* Wq_u = (const float*)d_in[4];
    const float* Wv_u = (const float*)d_in[5];
    const float* Wrk  = (const float*)d_in[6];
    const float* Wrq  = (const float*)d_in[7];
    const float* Wo   = (const float*)d_in[8];
    float* out = (float*)d_out;

    __half *p_wh, *p_hs, *p_p1, *p_q, *p_k, *p_vt, *p_y;
    cudaGetSymbolAddress((void**)&p_wh, g_wh);
    cudaGetSymbolAddress((void**)&p_hs, g_hs);
    cudaGetSymbolAddress((void**)&p_p1, g_p1);
    cudaGetSymbolAddress((void**)&p_q, g_q);
    cudaGetSymbolAddress((void**)&p_k, g_k);
    cudaGetSymbolAddress((void**)&p_vt, g_vt);
    cudaGetSymbolAddress((void**)&p_y, g_y);

    cudaFuncSetAttribute(f16_gemm_kernel,
                         cudaFuncAttributeMaxDynamicSharedMemorySize, GEMM_SMEM);
    cudaFuncSetAttribute(downproj_kernel,
                         cudaFuncAttributeMaxDynamicSharedMemorySize, GEMM_SMEM);
    cudaFuncSetAttribute(upproj_kernel,
                         cudaFuncAttributeMaxDynamicSharedMemorySize, GEMM_SMEM);
    cudaFuncSetAttribute(flash_f16_kernel,
                         cudaFuncAttributeMaxDynamicSharedMemorySize, FLASH_SMEM);

    // 1. fused setup
    setup_kernel<<<12800, dim3(32, 8)>>>(hs, Wkv, Wq_d, Wrk, Wk_u, Wq_u,
                                         Wrq, Wv_u, Wo, p_wh, p_hs);

    // 2. down-projection (kv_d|q_d -> p1, k_r rope -> g_k)
    downproj_kernel<<<dim3(12, 32), 128, GEMM_SMEM>>>(p_hs, p_wh, p_p1, p_k);

    // 3. up-projections (k_c, q_c scaled, q_r rope scaled, v transposed)
    upproj_kernel<<<dim3(40, 32), 128, GEMM_SMEM>>>(p_p1, p_wh, p_k, p_q, p_vt);

    // 4. causal flash attention (BQ=64, 2 CTAs/SM, register-P, pre-scaled Q)
    flash_f16_kernel<<<dim3(S_LEN / 64, BATCH * NHEADS), 128, FLASH_SMEM>>>(
        p_q, p_k, p_vt, p_y);

    // 5. output projection -> f32 out
    f16_gemm_kernel<<<dim3(16, 32), 128, GEMM_SMEM>>>(
        p_y, HDIM, p_wh + WO_OFF, 2048, out, HDIM, 2048, 2);
}

// round 17
// speedup vs baseline: 1.0096x; 1.0093x over previous
#include <cuda_runtime.h>
#include <cuda_fp16.h>
#include <math.h>
#include <stdint.h>

#define S_LEN   2048
#define BATCH   2
#define HDIM    2048
#define NHEADS  16
#define MROWS   (BATCH * S_LEN)   // 4096
#define ATT_SCALE 0.08838834764831845f

// ---------------- scratch ----------------
__device__ __half g_wh[8650752];   // transposed half weights
__device__ __half g_hs[8388608];   // hs [4096][2048]
__device__ __half g_p1[6291456];   // [4096][1536]; only cols 0..512 used now
__device__ __half g_q [8388608];   // [m][h*128+d]  (PRE-SCALED by 1/sqrt(d))
__device__ __half g_k [8388608];
__device__ __half g_vt[8388608];   // TRANSPOSED: [n=2048][m=4096]
__device__ __half g_y [8388608];
__device__ float  g_cs[65536];     // rope cos table [s][jj]  (2048 x 32)
__device__ float  g_sn[65536];     // rope sin table

#define WCAT_OFF 0u         // [1536][2048]
#define WKU_OFF  3145728u   // [1024][256]
#define WQU_OFF  3407872u
#define WRQ_OFF  3670016u
#define WVU_OFF  3932160u   // [2048][256]
#define WO_OFF   4456448u   // [2048][2048]

// ---------------- helpers ----------------
__device__ __forceinline__ void mma_f16(float* c, const uint32_t* a, const uint32_t* b) {
    asm volatile(
        "mma.sync.aligned.m16n8k16.row.col.f32.f16.f16.f32 "
        "{%0,%1,%2,%3}, {%4,%5,%6,%7}, {%8,%9}, {%0,%1,%2,%3};\n"
        : "+f"(c[0]), "+f"(c[1]), "+f"(c[2]), "+f"(c[3])
        : "r"(a[0]), "r"(a[1]), "r"(a[2]), "r"(a[3]), "r"(b[0]), "r"(b[1]));
}
__device__ __forceinline__ void ldsm4(uint32_t* r, uint32_t addr) {
    asm volatile("ldmatrix.sync.aligned.m8n8.x4.shared.b16 {%0,%1,%2,%3}, [%4];"
        : "=r"(r[0]), "=r"(r[1]), "=r"(r[2]), "=r"(r[3]) : "r"(addr));
}
__device__ __forceinline__ uint32_t pack2(float a, float b) {
    __half2 h = __floats2half2_rn(a, b);
    return *(uint32_t*)&h;
}
__device__ __forceinline__ uint32_t smem_u32(const void* p) {
    uint32_t a;
    asm("{ .reg .u64 t; cvta.to.shared.u64 t, %1; cvt.u32.u64 %0, t; }" : "=r"(a) : "l"(p));
    return a;
}
__device__ __forceinline__ void cp16(uint32_t dst, const void* src) {
    asm volatile("cp.async.cg.shared.global [%0], [%1], 16;" :: "r"(dst), "l"(src));
}
__device__ __forceinline__ void cp_commit() {
    asm volatile("cp.async.commit_group;" ::: "memory");
}
template<int N>
__device__ __forceinline__ void cp_wait() {
    asm volatile("cp.async.wait_group %0;" :: "n"(N) : "memory");
}

// ---------------- fused setup: weight transpose + hs convert + rope table ----
__global__ void setup_kernel(
    const float* __restrict__ hs,
    const float* __restrict__ wkv, const float* __restrict__ wqd,
    const float* __restrict__ wrk, const float* __restrict__ wku,
    const float* __restrict__ wqu, const float* __restrict__ wrq,
    const float* __restrict__ wvu, const float* __restrict__ wo,
    __half* __restrict__ wh, __half* __restrict__ dhs)
{
    const int b  = blockIdx.x;
    const int tx = threadIdx.x;
    const int ty = threadIdx.y;
    const int lt = ty * 32 + tx;

    if (b >= 12544) {                      // rope table: 256 blocks
        int idx = (b - 12544) * 256 + lt;  // [0, 65536)
        int s = idx >> 5, jj = idx & 31;
        float inv = exp2f(-0.41524101186092f * (float)jj);
        float sn, cs;
        sincosf((float)s * inv, &sn, &cs);
        g_cs[idx] = cs; g_sn[idx] = sn;
        return;
    }
    if (b >= 8448) {                       // hs -> half
        int i = (b - 8448) * 256 + lt;
        float4 a = ((const float4*)hs)[2 * i];
        float4 c = ((const float4*)hs)[2 * i + 1];
        uint4 u;
        u.x = pack2(a.x, a.y); u.y = pack2(a.z, a.w);
        u.z = pack2(c.x, c.y); u.w = pack2(c.z, c.w);
        *(uint4*)&dhs[8 * i] = u;
        return;
    }

    __shared__ float tile[32][33];
    const float* src; int ld, k0, n0, dK; uint32_t doff;
    if (b < 3072) {
        k0 = (b / 48) * 32; n0 = (b % 48) * 32; doff = WCAT_OFF; dK = 2048;
        if (n0 < 256)      { src = wkv + n0;         ld = 256; }
        else if (n0 < 512) { src = wqd + (n0 - 256); ld = 256; }
        else               { src = wrk + (n0 - 512); ld = 1024; }
    } else if (b < 3328) { int l = b - 3072; k0 = (l / 32) * 32; n0 = (l % 32) * 32;
        src = wku + n0; ld = 1024; doff = WKU_OFF; dK = 256;
    } else if (b < 3584) { int l = b - 3328; k0 = (l / 32) * 32; n0 = (l % 32) * 32;
        src = wqu + n0; ld = 1024; doff = WQU_OFF; dK = 256;
    } else if (b < 3840) { int l = b - 3584; k0 = (l / 32) * 32; n0 = (l % 32) * 32;
        src = wrq + n0; ld = 1024; doff = WRQ_OFF; dK = 256;
    } else if (b < 4352) { int l = b - 3840; k0 = (l / 64) * 32; n0 = (l % 64) * 32;
        src = wvu + n0; ld = 2048; doff = WVU_OFF; dK = 256;
    } else {               int l = b - 4352; k0 = (l / 64) * 32; n0 = (l % 64) * 32;
        src = wo + n0;  ld = 2048; doff = WO_OFF;  dK = 2048;
    }
#pragma unroll
    for (int rr = 0; rr < 4; rr++) {
        int r = ty * 4 + rr;
        tile[r][tx] = src[(size_t)(k0 + r) * ld + tx];
    }
    __syncthreads();
#pragma unroll
    for (int rr = 0; rr < 4; rr++) {
        int r = ty * 4 + rr;
        wh[doff + (size_t)(n0 + r) * dK + k0 + tx] = __float2half_rn(tile[tx][r]);
    }
}

// ---------------- fp16 GEMM: 128x128 tile, K64 stages, 2 buffers ------------
#define HKP 72
#define HSTG (2 * 128 * HKP)        // halves per stage = 18432
#define GEMM_SMEM (2 * HSTG * 2)    // 73728 B

// mode: 0 half plain, 1 half split, 2 f32 plain, 3 half V-transposed,
//       4 half rope-split.  oscale applied in modes 1 and 4.
__device__ __forceinline__ void gemm_f16_body(
    const __half* __restrict__ A, int lda,
    const __half* __restrict__ B, int ldb,
    void* Cv, int ldc, int K, int mode, int roff, float oscale,
    int bm, int bn, __half* smem)
{
    const uint32_t sb = smem_u32(smem);
    const int tid  = threadIdx.x;
    const int lane = tid & 31;
    const int wid  = tid >> 5;
    const int wm   = (wid & 1) * 64;
    const int wn   = (wid >> 1) * 64;
    const int g    = lane >> 2;
    const int j    = lane & 3;

    const int ra  = lane & 15;
    const int ka  = (lane >> 4) << 3;
    const int nb  = ((lane >> 4) << 3) + (lane & 7);
    const int kbo = lane & 8;

    float acc[4][8][4];
#pragma unroll
    for (int mt = 0; mt < 4; mt++)
#pragma unroll
        for (int nt = 0; nt < 8; nt++)
#pragma unroll
            for (int e = 0; e < 4; e++) acc[mt][nt][e] = 0.f;

    const int nstage = K >> 6;   // 64-wide K stages

    auto issue = [&](int it) {
        const int k0 = it << 6;
        const uint32_t base = sb + ((it & 1) * HSTG) * 2;
        // A: 128 rows x 64 halves = 1024 cp16; 8 per thread
#pragma unroll
        for (int i = 0; i < 8; i++) {
            int f = tid + (i << 7);
            int r = f >> 3, c = f & 7;
            cp16(base + (uint32_t)(r * HKP + c * 8) * 2,
                 A + (size_t)(bm + r) * lda + k0 + c * 8);
        }
        // B: 128 rows x 64 halves
#pragma unroll
        for (int i = 0; i < 8; i++) {
            int f = tid + (i << 7);
            int r = f >> 3, c = f & 7;
            cp16(base + (uint32_t)(128 * HKP + r * HKP + c * 8) * 2,
                 B + (size_t)(bn + r) * ldb + k0 + c * 8);
        }
        cp_commit();
    };

    issue(0);
    if (nstage > 1) issue(1);

    for (int it = 0; it < nstage; it++) {
        cp_wait<1>();
        __syncthreads();

        const uint32_t sA = sb + ((it & 1) * HSTG) * 2;
        const uint32_t sB = sA + 128 * HKP * 2;
#pragma unroll
        for (int s = 0; s < 4; s++) {
            const int kb = s * 16;
            uint32_t af[4][4], bf[4][4];
#pragma unroll
            for (int mt = 0; mt < 4; mt++)
                ldsm4(af[mt], sA + (uint32_t)((wm + mt * 16 + ra) * HKP + kb + ka) * 2);
#pragma unroll
            for (int p = 0; p < 4; p++)
                ldsm4(bf[p], sB + (uint32_t)((wn + p * 16 + nb) * HKP + kb + kbo) * 2);
#pragma unroll
            for (int mt = 0; mt < 4; mt++)
#pragma unroll
                for (int p = 0; p < 4; p++) {
                    mma_f16(acc[mt][2 * p],     af[mt], &bf[p][0]);
                    mma_f16(acc[mt][2 * p + 1], af[mt], &bf[p][2]);
                }
        }
        __syncthreads();
        if (it + 2 < nstage) issue(it + 2);
        else cp_commit();   // empty group keeps wait ledger aligned
    }

    // ---------------- epilogue ----------------
    if (mode == 4) {
        __half* C = (__half*)Cv;
#pragma unroll
        for (int mt = 0; mt < 4; mt++) {
            const int row = bm + wm + mt * 16 + g;
            const int s0 = row & 2047, s1 = (row + 8) & 2047;
#pragma unroll
            for (int nt = 0; nt < 4; nt++) {
                const int nr = bn + wn + nt * 8 + 2 * j - roff;
                const int jj = nr & 63;
                const int colx = ((nr >> 6) << 7) + jj + 64;
                const float c00 = g_cs[s0 * 32 + jj],     n00 = g_sn[s0 * 32 + jj];
                const float c01 = g_cs[s0 * 32 + jj + 1], n01 = g_sn[s0 * 32 + jj + 1];
                const float c10 = g_cs[s1 * 32 + jj],     n10 = g_sn[s1 * 32 + jj];
                const float c11 = g_cs[s1 * 32 + jj + 1], n11 = g_sn[s1 * 32 + jj + 1];
                float x1a = acc[mt][nt][0] * oscale,     x1b = acc[mt][nt][1] * oscale;
                float x2a = acc[mt][nt + 4][0] * oscale, x2b = acc[mt][nt + 4][1] * oscale;
                *(uint32_t*)(C + (size_t)row * ldc + colx) =
                    pack2(x1a * c00 - x2a * n00, x1b * c01 - x2b * n01);
                *(uint32_t*)(C + (size_t)row * ldc + colx + 32) =
                    pack2(x2a * c00 + x1a * n00, x2b * c01 + x1b * n01);
                x1a = acc[mt][nt][2] * oscale;     x1b = acc[mt][nt][3] * oscale;
                x2a = acc[mt][nt + 4][2] * oscale; x2b = acc[mt][nt + 4][3] * oscale;
                *(uint32_t*)(C + (size_t)(row + 8) * ldc + colx) =
                    pack2(x1a * c10 - x2a * n10, x1b * c11 - x2b * n11);
                *(uint32_t*)(C + (size_t)(row + 8) * ldc + colx + 32) =
                    pack2(x2a * c10 + x1a * n10, x2b * c11 + x1b * n11);
            }
        }
        return;
    }
#pragma unroll
    for (int mt = 0; mt < 4; mt++) {
        const int row = bm + wm + mt * 16 + g;
#pragma unroll
        for (int nt = 0; nt < 8; nt++) {
            const int n = bn + wn + nt * 8 + 2 * j;
            if (mode == 3) {
                __half* vt = (__half*)Cv;
                vt[(size_t)n * 4096 + row]           = __float2half_rn(acc[mt][nt][0]);
                vt[(size_t)(n + 1) * 4096 + row]     = __float2half_rn(acc[mt][nt][1]);
                vt[(size_t)n * 4096 + row + 8]       = __float2half_rn(acc[mt][nt][2]);
                vt[(size_t)(n + 1) * 4096 + row + 8] = __float2half_rn(acc[mt][nt][3]);
            } else if (mode == 2) {
                float* C = (float*)Cv;
                *(float2*)(C + (size_t)row * ldc + n) =
                    make_float2(acc[mt][nt][0], acc[mt][nt][1]);
                *(float2*)(C + (size_t)(row + 8) * ldc + n) =
                    make_float2(acc[mt][nt][2], acc[mt][nt][3]);
            } else if (mode == 1) {
                const int col = ((n >> 6) << 7) + (n & 63);
                __half* C = (__half*)Cv;
                *(uint32_t*)(C + (size_t)row * ldc + col) =
                    pack2(acc[mt][nt][0] * oscale, acc[mt][nt][1] * oscale);
                *(uint32_t*)(C + (size_t)(row + 8) * ldc + col) =
                    pack2(acc[mt][nt][2] * oscale, acc[mt][nt][3] * oscale);
            } else {
                __half* C = (__half*)Cv;
                *(uint32_t*)(C + (size_t)row * ldc + n) = pack2(acc[mt][nt][0], acc[mt][nt][1]);
                *(uint32_t*)(C + (size_t)(row + 8) * ldc + n) = pack2(acc[mt][nt][2], acc[mt][nt][3]);
            }
        }
    }
}

__global__ void __launch_bounds__(128, 2) f16_gemm_kernel(
    const __half* A, int lda, const __half* B, int ldb,
    void* C, int ldc, int K, int mode)
{
    extern __shared__ __half smh[];
    gemm_f16_body(A, lda, B, ldb, C, ldc, K, mode, 0, 1.f,
                  blockIdx.y * 128, blockIdx.x * 128, smh);
}

__global__ void __launch_bounds__(128, 2) downproj_kernel(
    const __half* __restrict__ hs, const __half* __restrict__ wh,
    __half* __restrict__ p1, __half* __restrict__ k)
{
    extern __shared__ __half smh[];
    const int bx = blockIdx.x;
    const int bm = blockIdx.y * 128;
    if (bx < 4)
        gemm_f16_body(hs, HDIM, wh + WCAT_OFF, 2048, p1, 1536, 2048, 0, 0, 1.f,
                      bm, bx << 7, smh);
    else
        gemm_f16_body(hs, HDIM, wh + WCAT_OFF, 2048, k, HDIM, 2048, 4, 512, 1.f,
                      bm, bx << 7, smh);
}

__global__ void __launch_bounds__(128, 2) upproj_kernel(
    const __half* __restrict__ p1, const __half* __restrict__ wh,
    __half* __restrict__ k, __half* __restrict__ q, __half* __restrict__ vt)
{
    extern __shared__ __half smh[];
    const int bx = blockIdx.x;
    const int bm = blockIdx.y * 128;
    const __half* A;
    const __half* B;
    void* C;
    int ldc, bn, mode;
    float sc;
    if (bx < 8) {
        A = p1;       B = wh + WKU_OFF; C = k;  ldc = HDIM; bn = bx << 7;        mode = 1; sc = 1.f;
    } else if (bx < 16) {
        A = p1 + 256; B = wh + WQU_OFF; C = q;  ldc = HDIM; bn = (bx - 8) << 7;  mode = 1; sc = ATT_SCALE;
    } else if (bx < 24) {
        A = p1 + 256; B = wh + WRQ_OFF; C = q;  ldc = HDIM; bn = (bx - 16) << 7; mode = 4; sc = ATT_SCALE;
    } else {
        A = p1;       B = wh + WVU_OFF; C = vt; ldc = 0;    bn = (bx - 24) << 7; mode = 3; sc = 1.f;
    }
    gemm_f16_body(A, 1536, B, 256, C, ldc, 256, mode, 0, sc, bm, bn, smh);
}

// ---------------- Flash attention: BQ=64, 128 thr, 2 CTAs/SM ----------------
// Q pre-scaled by 1/sqrt(d). P in registers (A-frag layout) — no Ps smem.
// smem halves: Ks 2x[64][136], Vt 2x[128][72] = 35840 h = 71680 B
#define FKS0 0
#define FKS1 8704
#define FVT0 17408
#define FVT1 26624
#define FLASH_SMEM (35840 * 2)

__global__ void __launch_bounds__(128, 2) flash_f16_kernel(
    const __half* __restrict__ Q, const __half* __restrict__ Kp,
    const __half* __restrict__ Vt, __half* __restrict__ Y)
{
    extern __shared__ __half smh[];
    const uint32_t sb = smem_u32(smh);

    const int tid  = threadIdx.x;
    const int lane = tid & 31;
    const int w    = tid >> 5;          // 0..3
    const int g    = lane >> 2;
    const int j    = lane & 3;
    const int bh   = blockIdx.y;
    const int b    = bh >> 4;
    const int h    = bh & 15;
    const int qt   = (int)gridDim.x - 1 - (int)blockIdx.x;
    const int q0   = qt << 6;

    const int ra  = lane & 15;
    const int ka  = (lane >> 4) << 3;
    const int nb  = ((lane >> 4) << 3) + (lane & 7);
    const int kbo = lane & 8;

    const __half* Kbase = Kp + (size_t)b * S_LEN * HDIM + h * 128;
    const __half* Vtb   = Vt + (size_t)h * 128 * 4096 + b * S_LEN;

    // ---- stage Q [64][136] into Ks0 region, extract persistent A-frags
    const __half* Qg = Q + (size_t)(b * S_LEN + q0) * HDIM + h * 128;
#pragma unroll
    for (int i = 0; i < 8; i++) {
        int f = tid + (i << 7);
        int r = f >> 4, c = f & 15;
        cp16(sb + (uint32_t)(r * 136 + c * 8) * 2, Qg + (size_t)r * HDIM + c * 8);
    }
    cp_commit();
    cp_wait<0>();
    __syncthreads();

    uint32_t qa[8][4];
#pragma unroll
    for (int ks = 0; ks < 8; ks++)
        ldsm4(qa[ks], sb + (uint32_t)((w * 16 + ra) * 136 + ks * 16 + ka) * 2);
    __syncthreads();

    auto issue_kv = [&](int t) {
        const int d = t & 1;
        const int kv0 = t << 6;
        const uint32_t kb = sb + (d ? FKS1 : FKS0) * 2;
        const uint32_t vb = sb + (d ? FVT1 : FVT0) * 2;
#pragma unroll
        for (int i = 0; i < 8; i++) {
            int f = tid + (i << 7);
            int r = f >> 4, c = f & 15;
            cp16(kb + (uint32_t)(r * 136 + c * 8) * 2,
                 Kbase + (size_t)(kv0 + r) * HDIM + c * 8);
        }
#pragma unroll
        for (int i = 0; i < 8; i++) {
            int f = tid + (i << 7);
            int r = f >> 3, c = f & 7;
            cp16(vb + (uint32_t)(r * 72 + c * 8) * 2,
                 Vtb + (size_t)r * 4096 + kv0 + c * 8);
        }
        cp_commit();
    };

    float o[16][4];
#pragma unroll
    for (int nt = 0; nt < 16; nt++)
#pragma unroll
        for (int e = 0; e < 4; e++) o[nt][e] = 0.f;
    float m0 = -1e30f, m1 = -1e30f, l0 = 0.f, l1 = 0.f;

    const int nkv = qt + 1;
    issue_kv(0);

    for (int t = 0; t < nkv; t++) {
        const int kv0 = t << 6;
        if (t + 1 < nkv) issue_kv(t + 1);
        else cp_commit();
        cp_wait<1>();
        __syncthreads();

        const uint32_t sbK = sb + ((t & 1) ? FKS1 : FKS0) * 2;
        const uint32_t sbV = sb + ((t & 1) ? FVT1 : FVT0) * 2;

        // ---- S = Q K^T  (Q pre-scaled)
        float s[8][4];
#pragma unroll
        for (int nt = 0; nt < 8; nt++)
#pragma unroll
            for (int e = 0; e < 4; e++) s[nt][e] = 0.f;
#pragma unroll
        for (int ks = 0; ks < 8; ks++) {
            const int kc = ks * 16;
            uint32_t bf[4][4];
#pragma unroll
            for (int p = 0; p < 4; p++)
                ldsm4(bf[p], sbK + (uint32_t)((p * 16 + nb) * 136 + kc + kbo) * 2);
#pragma unroll
            for (int p = 0; p < 4; p++) {
                mma_f16(s[2 * p],     qa[ks], &bf[p][0]);
                mma_f16(s[2 * p + 1], qa[ks], &bf[p][2]);
            }
        }

        // ---- online softmax (fp32); P packed straight into A-frag registers
        const bool needm = (t == nkv - 1);
        const int gr0 = q0 + w * 16 + g;
        const int gr1 = gr0 + 8;
        float tm0 = -1e30f, tm1 = -1e30f;
#pragma unroll
        for (int nt = 0; nt < 8; nt++) {
            int c0 = kv0 + nt * 8 + 2 * j;
#pragma unroll
            for (int e = 0; e < 2; e++) {
                float v0 = s[nt][e];
                float v1 = s[nt][2 + e];
                if (needm) {
                    if (c0 + e > gr0) v0 = -1e30f;
                    if (c0 + e > gr1) v1 = -1e30f;
                }
                s[nt][e] = v0; s[nt][2 + e] = v1;
                tm0 = fmaxf(tm0, v0); tm1 = fmaxf(tm1, v1);
            }
        }
        tm0 = fmaxf(tm0, __shfl_xor_sync(0xffffffffu, tm0, 1));
        tm0 = fmaxf(tm0, __shfl_xor_sync(0xffffffffu, tm0, 2));
        tm1 = fmaxf(tm1, __shfl_xor_sync(0xffffffffu, tm1, 1));
        tm1 = fmaxf(tm1, __shfl_xor_sync(0xffffffffu, tm1, 2));
        const bool up0 = tm0 > m0, up1 = tm1 > m1;
        const float mn0 = up0 ? tm0 : m0;
        const float mn1 = up1 ? tm1 : m1;
        const float cr0 = up0 ? __expf(m0 - mn0) : 1.f;
        const float cr1 = up1 ? __expf(m1 - mn1) : 1.f;
        float sum0 = 0.f, sum1 = 0.f;
        uint32_t pa[4][4];
#pragma unroll
        for (int nt = 0; nt < 8; nt++) {
            float p0 = __expf(s[nt][0] - mn0);
            float p1 = __expf(s[nt][1] - mn0);
            float p2 = __expf(s[nt][2] - mn1);
            float p3 = __expf(s[nt][3] - mn1);
            sum0 += p0 + p1; sum1 += p2 + p3;
            const int kk = nt >> 1;
            if (nt & 1) { pa[kk][2] = pack2(p0, p1); pa[kk][3] = pack2(p2, p3); }
            else        { pa[kk][0] = pack2(p0, p1); pa[kk][1] = pack2(p2, p3); }
        }
        sum0 += __shfl_xor_sync(0xffffffffu, sum0, 1);
        sum0 += __shfl_xor_sync(0xffffffffu, sum0, 2);
        sum1 += __shfl_xor_sync(0xffffffffu, sum1, 1);
        sum1 += __shfl_xor_sync(0xffffffffu, sum1, 2);
        l0 = l0 * cr0 + sum0; l1 = l1 * cr1 + sum1;
        m0 = mn0; m1 = mn1;
        if (__any_sync(0xffffffffu, up0 || up1)) {
#pragma unroll
            for (int nt = 0; nt < 16; nt++) {
                o[nt][0] *= cr0; o[nt][1] *= cr0;
                o[nt][2] *= cr1; o[nt][3] *= cr1;
            }
        }

        // ---- O += P V  (P from registers; V via ldmatrix)
#pragma unroll
        for (int kk = 0; kk < 4; kk++) {
            const int kc = kk * 16;
            uint32_t bv[4];
#pragma unroll
            for (int p = 0; p < 8; p++) {
                ldsm4(bv, sbV + (uint32_t)((p * 16 + nb) * 72 + kc + kbo) * 2);
                mma_f16(o[2 * p],     pa[kk], &bv[0]);
                mma_f16(o[2 * p + 1], pa[kk], &bv[2]);
            }
        }
        __syncthreads();  // protect K/V buffers before next issue
    }

    // ---- epilogue -> y half
    const float inv0 = 1.f / l0, inv1 = 1.f / l1;
    const int gr0 = q0 + w * 16 + g;
    __half* Y0 = Y + (size_t)(b * S_LEN + gr0) * HDIM + h * 128;
    __half* Y1 = Y + (size_t)(b * S_LEN + gr0 + 8) * HDIM + h * 128;
#pragma unroll
    for (int nt = 0; nt < 16; nt++) {
        const int c = nt * 8 + 2 * j;
        *(uint32_t*)&Y0[c] = pack2(o[nt][0] * inv0, o[nt][1] * inv0);
        *(uint32_t*)&Y1[c] = pack2(o[nt][2] * inv1, o[nt][3] * inv1);
    }
}

// ---------------- launch ----------------
extern "C" void kernel_launch(void* const* d_in, const int* in_sizes, int n_in,
                              void* d_out, int out_size)
{
    const float* hs   = (const float*)d_in[0];
    const float* Wkv  = (const float*)d_in[1];
    const float* Wq_d = (const float*)d_in[2];
    const float* Wk_u = (const float*)d_in[3];
    const float* Wq_u = (const float*)d_in[4];
    const float* Wv_u = (const float*)d_in[5];
    const float* Wrk  = (const float*)d_in[6];
    const float* Wrq  = (const float*)d_in[7];
    const float* Wo   = (const float*)d_in[8];
    float* out = (float*)d_out;

    __half *p_wh, *p_hs, *p_p1, *p_q, *p_k, *p_vt, *p_y;
    cudaGetSymbolAddress((void**)&p_wh, g_wh);
    cudaGetSymbolAddress((void**)&p_hs, g_hs);
    cudaGetSymbolAddress((void**)&p_p1, g_p1);
    cudaGetSymbolAddress((void**)&p_q, g_q);
    cudaGetSymbolAddress((void**)&p_k, g_k);
    cudaGetSymbolAddress((void**)&p_vt, g_vt);
    cudaGetSymbolAddress((void**)&p_y, g_y);

    cudaFuncSetAttribute(f16_gemm_kernel,
                         cudaFuncAttributeMaxDynamicSharedMemorySize, GEMM_SMEM);
    cudaFuncSetAttribute(downproj_kernel,
                         cudaFuncAttributeMaxDynamicSharedMemorySize, GEMM_SMEM);
    cudaFuncSetAttribute(upproj_kernel,
                         cudaFuncAttributeMaxDynamicSharedMemorySize, GEMM_SMEM);
    cudaFuncSetAttribute(flash_f16_kernel,
                         cudaFuncAttributeMaxDynamicSharedMemorySize, FLASH_SMEM);

    // 1. fused setup
    setup_kernel<<<12800, dim3(32, 8)>>>(hs, Wkv, Wq_d, Wrk, Wk_u, Wq_u,
                                         Wrq, Wv_u, Wo, p_wh, p_hs);

    // 2. down-projection (kv_d|q_d -> p1, k_r rope -> g_k)
    downproj_kernel<<<dim3(12, 32), 128, GEMM_SMEM>>>(p_hs, p_wh, p_p1, p_k);

    // 3. up-projections (k_c, q_c scaled, q_r rope scaled, v transposed)
    upproj_kernel<<<dim3(40, 32), 128, GEMM_SMEM>>>(p_p1, p_wh, p_k, p_q, p_vt);

    // 4. causal flash attention (BQ=64, 2 CTAs/SM, register-P, pre-scaled Q)
    flash_f16_kernel<<<dim3(S_LEN / 64, BATCH * NHEADS), 128, FLASH_SMEM>>>(
        p_q, p_k, p_vt, p_y);

    // 5. output projection -> f32 out
    f16_gemm_kernel<<<dim3(16, 32), 128, GEMM_SMEM>>>(
        p_y, HDIM, p_wh + WO_OFF, 2048, out, HDIM, 2048, 2);
}